// round 13
// baseline (speedup 1.0000x reference)
#include <cuda_runtime.h>
#include <cuda_bf16.h>
#include <stdint.h>

#define TS   512
#define BA   64
#define DI   512
#define HID  512
#define NG   2048          // 4 gates * HID, INTERLEAVED: c' = hid*4 + gate (0=i,1=f,2=o,3=c)
#define TBM  (TS*BA)
#define GRP  4             // independent batch groups
#define BPG  32            // blocks per group
#define NLSTM 128          // lstm blocks (bids 0..127)
#define NWKR  168          // gemm worker blocks (bids 128..295)

// gemm pipeline: k-chunk 16, pad rows to 24 elems, 3 stages
#define KCH   16
#define GPAD  24
#define GTILE (128*GPAD)               // elems per array per stage (3072)
#define GSTG  (4*GTILE)                // elems per stage (4 arrays)
#define GSMEM (3*GSTG*2)               // bytes total (73728)

// ----------------- device-global scratch -----------------
static __device__ __align__(16) __nv_bfloat16 g_Ahi[(size_t)TBM*DI];
static __device__ __align__(16) __nv_bfloat16 g_Alo[(size_t)TBM*DI];
static __device__ __align__(16) __nv_bfloat16 g_WxThi[(size_t)NG*DI];   // [c'][d], K-major
static __device__ __align__(16) __nv_bfloat16 g_WxTlo[(size_t)NG*DI];
static __device__ __align__(16) __nv_bfloat16 g_WhThi[(size_t)NG*HID];  // [c'][k], K-major
static __device__ __align__(16) float         g_bias[NG];               // c' order
static __device__ __align__(16) float         g_X[(size_t)TBM*NG];      // c' order
static __device__ __align__(16) __nv_bfloat16 g_HG[2][GRP][16*HID];     // per-group H, frag order
static __device__ __align__(128) int g_pcnt[GRP][32];   // per-producer monotonic counters (1 line/group)
static __device__ int g_Xflag[256*32];     // per-row-block (2 timesteps) counters, padded

// ----------------- helpers -----------------
__device__ __forceinline__ void split_bf16(float v, __nv_bfloat16& hi, __nv_bfloat16& lo) {
    hi = __float2bfloat16(v);
    lo = __float2bfloat16(v - __bfloat162float(hi));
}

__device__ __forceinline__ void mma16816(float* c,
                                         uint32_t a0, uint32_t a1, uint32_t a2, uint32_t a3,
                                         uint32_t b0, uint32_t b1) {
    asm volatile(
        "mma.sync.aligned.m16n8k16.row.col.f32.bf16.bf16.f32 "
        "{%0,%1,%2,%3},{%4,%5,%6,%7},{%8,%9},{%0,%1,%2,%3};\n"
        : "+f"(c[0]), "+f"(c[1]), "+f"(c[2]), "+f"(c[3])
        : "r"(a0), "r"(a1), "r"(a2), "r"(a3), "r"(b0), "r"(b1));
}

__device__ __forceinline__ uint32_t smem_u32(const void* p) {
    return (uint32_t)__cvta_generic_to_shared(p);
}

__device__ __forceinline__ void ldsm4(uint32_t* r, uint32_t addr) {
    asm volatile("ldmatrix.sync.aligned.m8n8.x4.shared.b16 {%0,%1,%2,%3}, [%4];"
        : "=r"(r[0]), "=r"(r[1]), "=r"(r[2]), "=r"(r[3]) : "r"(addr));
}

__device__ __forceinline__ float sigf(float x) { return 1.f / (1.f + __expf(-x)); }
__device__ __forceinline__ float tanhfast(float x) {
    float ax = fminf(fmaxf(x, -15.f), 15.f);
    float e  = __expf(2.f * ax);
    return (e - 1.f) / (e + 1.f);
}

__device__ __forceinline__ void st_cg_b16(__nv_bfloat16* p, __nv_bfloat16 v) {
    unsigned short u = *(unsigned short*)&v;
    asm volatile("st.global.cg.b16 [%0], %1;" :: "l"(p), "h"(u) : "memory");
}

__device__ __forceinline__ void cpa16(void* dst, const void* src) {
    uint32_t s = smem_u32(dst);
    asm volatile("cp.async.cg.shared.global [%0], [%1], 16;\n" :: "r"(s), "l"(src));
}
__device__ __forceinline__ void cpa_commit() { asm volatile("cp.async.commit_group;\n"); }
template<int N> __device__ __forceinline__ void cpa_wait() {
    asm volatile("cp.async.wait_group %0;\n" :: "n"(N));
}

// ----------------- distributed barrier: single-writer counters + ballot wait -----------------
// arrive: after __syncthreads, thread 0 release-stores its block's counter = next
__device__ __forceinline__ void dist_arrive(int g, int j, int next) {
    __syncthreads();
    if (threadIdx.x == 0) {
        asm volatile("st.release.gpu.global.s32 [%0], %1;"
                     :: "l"(&g_pcnt[g][j]), "r"(next) : "memory");
    }
}
// wait: warp 0 lane-parallel poll of all 32 counters (one coalesced line), ballot until all >= target
__device__ __forceinline__ void dist_wait(int g, int target) {
    if (threadIdx.x < 32) {
        int v;
        unsigned full;
        do {
            asm volatile("ld.acquire.gpu.global.s32 %0, [%1];"
                         : "=r"(v) : "l"(&g_pcnt[g][threadIdx.x]) : "memory");
            full = __ballot_sync(0xffffffffu, v >= target);
        } while (full != 0xffffffffu);
    }
    __syncthreads();
}

// all-threads poll: X row-block rb (2 timesteps) complete when counter == 16
__device__ __forceinline__ void wait_x(int rb) {
    const int* f = &g_Xflag[rb*32];
    int v;
    do {
        asm volatile("ld.acquire.gpu.global.s32 %0, [%1];" : "=r"(v) : "l"(f) : "memory");
    } while (v < 16);
}

// ----------------- init -----------------
__global__ void k_init() {
    int i = blockIdx.x * blockDim.x + threadIdx.x;
    if (i < 2 * GRP * 16 * HID) ((__nv_bfloat16*)g_HG)[i] = __float2bfloat16(0.f);
    if (i < GRP*32) ((int*)g_pcnt)[i] = 0;
    if (i < 256*32) g_Xflag[i] = 0;
}

// ----------------- inputs -> split bf16 -----------------
__global__ void k_conv_in(const float* __restrict__ in) {
    size_t i = (size_t)blockIdx.x * blockDim.x + threadIdx.x;
    const size_t n4 = (size_t)TBM * DI / 4;
    if (i >= n4) return;
    float4 v = reinterpret_cast<const float4*>(in)[i];
    __nv_bfloat16 h0,h1,h2,h3,l0,l1,l2,l3;
    split_bf16(v.x, h0, l0); split_bf16(v.y, h1, l1);
    split_bf16(v.z, h2, l2); split_bf16(v.w, h3, l3);
    __nv_bfloat162* ph = reinterpret_cast<__nv_bfloat162*>(g_Ahi + 4*i);
    __nv_bfloat162* pl = reinterpret_cast<__nv_bfloat162*>(g_Alo + 4*i);
    ph[0] = __halves2bfloat162(h0, h1); ph[1] = __halves2bfloat162(h2, h3);
    pl[0] = __halves2bfloat162(l0, l1); pl[1] = __halves2bfloat162(l2, l3);
}

// ----------------- weights -> bf16, transposed, gate-interleaved c' = h*4+g -----------------
__global__ void k_conv_w(const float* __restrict__ Wxi, const float* __restrict__ Wxf,
                         const float* __restrict__ Wxo, const float* __restrict__ Wxc,
                         const float* __restrict__ Whi, const float* __restrict__ Whf,
                         const float* __restrict__ Who, const float* __restrict__ Whc,
                         const float* __restrict__ bi,  const float* __restrict__ bff,
                         const float* __restrict__ bo,  const float* __restrict__ bc) {
    const int NW = NG * DI;
    int stride = gridDim.x * blockDim.x;
    for (int i = blockIdx.x * blockDim.x + threadIdx.x; i < 2*NW + NG; i += stride) {
        if (i < NW) {                          // WxT[c'][d], split
            int c = i >> 9, d = i & 511;
            int h = c >> 2, gg = c & 3;
            const float* W = gg == 0 ? Wxi : (gg == 1 ? Wxf : (gg == 2 ? Wxo : Wxc));
            __nv_bfloat16 hi, lo; split_bf16(W[d*HID + h], hi, lo);
            g_WxThi[i] = hi; g_WxTlo[i] = lo;
        } else if (i < 2*NW) {                 // WhT[c'][k], hi only
            int jj = i - NW;
            int c = jj >> 9, k = jj & 511;
            int h = c >> 2, gg = c & 3;
            const float* W = gg == 0 ? Whi : (gg == 1 ? Whf : (gg == 2 ? Who : Whc));
            g_WhThi[jj] = __float2bfloat16(W[k*HID + h]);
        } else {                               // bias, c' order
            int c = i - 2*NW;
            int h = c >> 2, gg = c & 3;
            const float* bb = gg == 0 ? bi : (gg == 1 ? bff : (gg == 2 ? bo : bc));
            g_bias[c] = bb[h];
        }
    }
}

// ----------------- gemm tile (device fn; one 128x128 output tile) -----------------
__device__ __forceinline__ void gx_prefetch(__nv_bfloat16* smx, int ck, int s,
                                            int row0, int col0, int lr, int lh) {
    size_t gA = (size_t)(row0 + lr) * DI + ck*KCH + lh*8;
    size_t gB = (size_t)(col0 + lr) * DI + ck*KCH + lh*8;
    int so = lr*GPAD + lh*8;
    __nv_bfloat16* base = smx + (size_t)s*GSTG;
    cpa16(base + 0*GTILE + so, g_Ahi   + gA);
    cpa16(base + 1*GTILE + so, g_Alo   + gA);
    cpa16(base + 2*GTILE + so, g_WxThi + gB);
    cpa16(base + 3*GTILE + so, g_WxTlo + gB);
}

__device__ void gemm_tile(__nv_bfloat16* smx, int by, int bx) {
    const int tid = threadIdx.x, w = tid >> 5, l = tid & 31;
    const int wm = w & 3, wn = w >> 2, r = l >> 2, q = l & 3;
    const int row0 = by * 128, col0 = bx * 128;
    const int lr = tid >> 1, lh = tid & 1;
    const int grp = l >> 3, rr = l & 7;
    const int NK = DI / KCH;   // 32

    float acc[2][8][4];
    #pragma unroll
    for (int a = 0; a < 2; a++)
        #pragma unroll
        for (int b = 0; b < 8; b++)
            #pragma unroll
            for (int c = 0; c < 4; c++) acc[a][b][c] = 0.f;

    gx_prefetch(smx, 0, 0, row0, col0, lr, lh);
    cpa_commit();
    gx_prefetch(smx, 1, 1, row0, col0, lr, lh);
    cpa_commit();

    for (int ck = 0; ck < NK; ck++) {
        cpa_wait<1>();
        __syncthreads();

        if (ck + 2 < NK) {
            gx_prefetch(smx, ck + 2, (ck + 2) % 3, row0, col0, lr, lh);
            cpa_commit();
        } else {
            cpa_commit();
        }

        const __nv_bfloat16* base = smx + (size_t)(ck % 3)*GSTG;
        const __nv_bfloat16* Ah_s = base + 0*GTILE;
        const __nv_bfloat16* Al_s = base + 1*GTILE;
        const __nv_bfloat16* Bh_s = base + 2*GTILE;
        const __nv_bfloat16* Bl_s = base + 3*GTILE;

        const int acol = (grp >> 1)*8;
        uint32_t Ahf[2][4], Alf[2][4];
        #pragma unroll
        for (int mt = 0; mt < 2; mt++) {
            int arow = wm*32 + mt*16 + (grp & 1)*8 + rr;
            ldsm4(Ahf[mt], smem_u32(&Ah_s[arow*GPAD + acol]));
            ldsm4(Alf[mt], smem_u32(&Al_s[arow*GPAD + acol]));
        }
        #pragma unroll
        for (int np = 0; np < 4; np++) {
            int brow = wn*64 + np*16 + (grp >> 1)*8 + rr;
            int bcol = (grp & 1)*8;
            uint32_t bh[4], bl[4];
            ldsm4(bh, smem_u32(&Bh_s[brow*GPAD + bcol]));
            ldsm4(bl, smem_u32(&Bl_s[brow*GPAD + bcol]));
            #pragma unroll
            for (int mt = 0; mt < 2; mt++) {
                float* a0 = acc[mt][np*2];
                float* a1 = acc[mt][np*2 + 1];
                mma16816(a0, Ahf[mt][0], Ahf[mt][1], Ahf[mt][2], Ahf[mt][3], bh[0], bh[1]);
                mma16816(a0, Alf[mt][0], Alf[mt][1], Alf[mt][2], Alf[mt][3], bh[0], bh[1]);
                mma16816(a0, Ahf[mt][0], Ahf[mt][1], Ahf[mt][2], Ahf[mt][3], bl[0], bl[1]);
                mma16816(a1, Ahf[mt][0], Ahf[mt][1], Ahf[mt][2], Ahf[mt][3], bh[2], bh[3]);
                mma16816(a1, Alf[mt][0], Alf[mt][1], Alf[mt][2], Alf[mt][3], bh[2], bh[3]);
                mma16816(a1, Ahf[mt][0], Ahf[mt][1], Ahf[mt][2], Ahf[mt][3], bl[2], bl[3]);
            }
        }
    }

    #pragma unroll
    for (int mt = 0; mt < 2; mt++) {
        #pragma unroll
        for (int nt = 0; nt < 8; nt++) {
            int grow = row0 + wm*32 + mt*16 + r;
            int gcol = col0 + wn*64 + nt*8 + 2*q;
            float2 bb = *(const float2*)&g_bias[gcol];
            float2 v0 = make_float2(acc[mt][nt][0] + bb.x, acc[mt][nt][1] + bb.y);
            float2 v1 = make_float2(acc[mt][nt][2] + bb.x, acc[mt][nt][3] + bb.y);
            *(float2*)&g_X[(size_t)grow * NG + gcol]       = v0;
            *(float2*)&g_X[(size_t)(grow + 8) * NG + gcol] = v1;
        }
    }

    // publish: row-block by ready when all 16 col blocks arrive
    __syncthreads();
    if (threadIdx.x == 0) {
        asm volatile("red.release.gpu.global.add.s32 [%0], %1;"
                     :: "l"(&g_Xflag[by*32]), "r"(1) : "memory");
    }
    // drain committed cp.asyncs before smem reuse on next tile
    cpa_wait<0>();
    __syncthreads();
}

// ----------------- lstm role (device fn) -----------------
__device__ void lstm_body(float* __restrict__ out, char* dynsm, int blk) {
    __nv_bfloat16* sH = (__nv_bfloat16*)dynsm;

    const int tid = threadIdx.x, w = tid >> 5, l = tid & 31;
    const int r = l >> 2, q = l & 3;
    const int g = blk >> 5, j = blk & 31;

    // Wh-hi fragments in registers: warp's col = j*64 + w*8 + r, all 32 k-frags
    uint32_t Bh[32][2];
    {
        const __nv_bfloat16* wp = g_WhThi + (size_t)(j*64 + w*8 + r) * HID;
        #pragma unroll
        for (int ktl = 0; ktl < 32; ktl++) {
            int kg = ktl * 16;
            Bh[ktl][0] = *(const uint32_t*)(wp + kg + 2*q);
            Bh[ktl][1] = *(const uint32_t*)(wp + kg + 2*q + 8);
        }
    }

    float C = 0.f;
    const int myrow = (q & 1) ? (r + 8) : r;
    const int hid   = j*16 + w*2 + (q >> 1);
    const int kk    = hid & 15;
    const int plane = ((myrow & 7) << 2) | ((kk & 7) >> 1);
    const int preg  = ((myrow >> 3) & 1) | ((kk >> 3) << 1);
    const int widx  = (j*32 + plane)*8 + preg*2 + (kk & 1);
    const int c0    = j*64 + w*8 + 2*q;

    // wait for X row-block 0, then prefetch t=0 seeds
    wait_x(0);
    float2 sd01, sd23;
    {
        size_t row0 = (size_t)(g*16 + r);
        sd01 = __ldcg((const float2*)&g_X[row0 * NG + c0]);
        sd23 = __ldcg((const float2*)&g_X[(row0 + 8) * NG + c0]);
    }

    for (int t = 0; t < TS; t++) {
        const int rb = t & 1;
        float acc[4], acc2[4];
        acc[0] = sd01.x; acc[1] = sd01.y; acc[2] = sd23.x; acc[3] = sd23.y;
        acc2[0] = acc2[1] = acc2[2] = acc2[3] = 0.f;

        if (t > 0) dist_wait(g, t);   // all 32 producers of this group published H(t-1)

        // chunked cooperative H copy: 2 x 8KB via cp.async
        const __nv_bfloat16* Hg = g_HG[rb][g];
        cpa16(sH + (size_t)tid*8,         Hg + (size_t)tid*8);
        cpa16(sH + (size_t)(tid+256)*8,   Hg + (size_t)(tid+256)*8);
        cpa_commit();
        cpa16(sH + (size_t)(tid+512)*8,   Hg + (size_t)(tid+512)*8);
        cpa16(sH + (size_t)(tid+768)*8,   Hg + (size_t)(tid+768)*8);
        cpa_commit();

        // prefetch seeds for t+1 (new X row-block every 2 steps; poll its flag)
        if (t + 1 < TS) {
            if (((t + 1) & 1) == 0) wait_x((t + 1) >> 1);
            size_t rown = (size_t)((t + 1)*BA + g*16 + r);
            sd01 = __ldcg((const float2*)&g_X[rown * NG + c0]);
            sd23 = __ldcg((const float2*)&g_X[(rown + 8) * NG + c0]);
        }

        cpa_wait<1>();
        __syncthreads();
        #pragma unroll
        for (int ktl = 0; ktl < 16; ktl += 2) {
            uint4 a0 = *(const uint4*)(sH + (size_t)(ktl*32 + l)*8);
            uint4 a1 = *(const uint4*)(sH + (size_t)((ktl + 1)*32 + l)*8);
            mma16816(acc,  a0.x, a0.y, a0.z, a0.w, Bh[ktl][0],   Bh[ktl][1]);
            mma16816(acc2, a1.x, a1.y, a1.z, a1.w, Bh[ktl+1][0], Bh[ktl+1][1]);
        }
        cpa_wait<0>();
        __syncthreads();
        #pragma unroll
        for (int ktl = 16; ktl < 32; ktl += 2) {
            uint4 a0 = *(const uint4*)(sH + (size_t)(ktl*32 + l)*8);
            uint4 a1 = *(const uint4*)(sH + (size_t)((ktl + 1)*32 + l)*8);
            mma16816(acc,  a0.x, a0.y, a0.z, a0.w, Bh[ktl][0],   Bh[ktl][1]);
            mma16816(acc2, a1.x, a1.y, a1.z, a1.w, Bh[ktl+1][0], Bh[ktl+1][1]);
        }
        acc[0] += acc2[0]; acc[1] += acc2[1]; acc[2] += acc2[2]; acc[3] += acc2[3];

        // gather 4 gates into one thread via lane-pair shuffle
        float s0 = __shfl_xor_sync(0xffffffffu, acc[0], 1);
        float s1 = __shfl_xor_sync(0xffffffffu, acc[1], 1);
        float s2 = __shfl_xor_sync(0xffffffffu, acc[2], 1);
        float s3 = __shfl_xor_sync(0xffffffffu, acc[3], 1);
        float xi, xf, xo, xc;
        if (q & 1) { xi = s2;     xf = s3;     xo = acc[2]; xc = acc[3]; }
        else       { xi = acc[0]; xf = acc[1]; xo = s0;     xc = s1;     }

        float I  = sigf(xi), F = sigf(xf), O = sigf(xo);
        float Ct = tanhfast(xc);
        C = F*C + I*Ct;
        float Hn = O * tanhfast(C);

        st_cg_b16(&g_HG[rb ^ 1][g][widx], __float2bfloat16(Hn));
        dist_arrive(g, j, t + 1);   // syncthreads inside (orders H stores + sH reuse)

        // off the critical path: fp32 outputs
        int batch = g*16 + myrow;
        out[((size_t)t*BA + batch)*HID + hid] = Hn;
        if (t == TS - 1) {
            out[(size_t)TS*BA*HID + (size_t)batch*HID + hid]                  = Hn;
            out[(size_t)TS*BA*HID + (size_t)BA*HID + (size_t)batch*HID + hid] = C;
        }
    }
}

// ----------------- fused kernel: lstm blocks 0..127, gemm workers 128..295 -----------------
__global__ __launch_bounds__(256, 2) void k_fused(float* __restrict__ out) {
    extern __shared__ char dynsm[];
    const int bid = blockIdx.x;
    if (bid < NLSTM) {
        lstm_body(out, dynsm, bid);
    } else {
        const int wkr = bid - NLSTM;
        __nv_bfloat16* smx = (__nv_bfloat16*)dynsm;
        for (int tile = wkr; tile < 256*16; tile += NWKR) {
            gemm_tile(smx, tile >> 4, tile & 15);
        }
    }
}

// ----------------- launch -----------------
extern "C" void kernel_launch(void* const* d_in, const int* in_sizes, int n_in,
                              void* d_out, int out_size) {
    const float* inp = (const float*)d_in[0];
    const float* Wxi = (const float*)d_in[1];
    const float* Whi = (const float*)d_in[2];
    const float* bi  = (const float*)d_in[3];
    const float* Wxf = (const float*)d_in[4];
    const float* Whf = (const float*)d_in[5];
    const float* bf  = (const float*)d_in[6];
    const float* Wxo = (const float*)d_in[7];
    const float* Who = (const float*)d_in[8];
    const float* bo  = (const float*)d_in[9];
    const float* Wxc = (const float*)d_in[10];
    const float* Whc = (const float*)d_in[11];
    const float* bc  = (const float*)d_in[12];
    float* out = (float*)d_out;

    static int inited = 0;
    if (!inited) {
        cudaFuncSetAttribute(k_fused, cudaFuncAttributeMaxDynamicSharedMemorySize, GSMEM);
        inited = 1;
    }

    k_init<<<256, 256>>>();
    k_conv_in<<<16384, 256>>>(inp);
    k_conv_w<<<2048, 256>>>(Wxi, Wxf, Wxo, Wxc, Whi, Whf, Who, Whc, bi, bf, bo, bc);
    k_fused<<<NLSTM + NWKR, 256, GSMEM>>>(out);
}

// round 14
// speedup vs baseline: 1.1636x; 1.1636x over previous
#include <cuda_runtime.h>
#include <cuda_bf16.h>
#include <stdint.h>

#define TS   512
#define BA   64
#define DI   512
#define HID  512
#define NG   2048          // 4 gates * HID, INTERLEAVED: c' = hid*4 + gate (0=i,1=f,2=o,3=c)
#define TBM  (TS*BA)
#define GRP  4             // independent batch groups
#define BPG  32            // blocks per group
#define NLSTM 128          // lstm blocks (bids 0..127)
#define NWKR  168          // gemm worker blocks (bids 128..295)

// gemm pipeline: k-chunk 16, pad rows to 24 elems, 3 stages
#define KCH   16
#define GPAD  24
#define GTILE (128*GPAD)               // elems per array per stage (3072)
#define GSTG  (4*GTILE)                // elems per stage (4 arrays)
#define GSMEM (3*GSTG*2)               // bytes total (73728)

// ----------------- device-global scratch -----------------
static __device__ __align__(16) __nv_bfloat16 g_Ahi[(size_t)TBM*DI];
static __device__ __align__(16) __nv_bfloat16 g_Alo[(size_t)TBM*DI];
static __device__ __align__(16) __nv_bfloat16 g_WxThi[(size_t)NG*DI];   // [c'][d], K-major
static __device__ __align__(16) __nv_bfloat16 g_WxTlo[(size_t)NG*DI];
static __device__ __align__(16) __nv_bfloat16 g_WhThi[(size_t)NG*HID];  // [c'][k], K-major
static __device__ __align__(16) float         g_bias[NG];               // c' order
static __device__ __align__(16) float         g_X[(size_t)TBM*NG];      // c' order
static __device__ __align__(16) __nv_bfloat16 g_HG[2][GRP][16*HID];     // per-group H, frag order
static __device__ int g_cntG[GRP*32];      // padded arrival counters
static __device__ int g_phaseG[GRP*32];    // padded phase flags
static __device__ int g_Xflag[256*32];     // per-row-block (2 timesteps) counters, padded

// ----------------- helpers -----------------
__device__ __forceinline__ void split_bf16(float v, __nv_bfloat16& hi, __nv_bfloat16& lo) {
    hi = __float2bfloat16(v);
    lo = __float2bfloat16(v - __bfloat162float(hi));
}

__device__ __forceinline__ void mma16816(float* c,
                                         uint32_t a0, uint32_t a1, uint32_t a2, uint32_t a3,
                                         uint32_t b0, uint32_t b1) {
    asm volatile(
        "mma.sync.aligned.m16n8k16.row.col.f32.bf16.bf16.f32 "
        "{%0,%1,%2,%3},{%4,%5,%6,%7},{%8,%9},{%0,%1,%2,%3};\n"
        : "+f"(c[0]), "+f"(c[1]), "+f"(c[2]), "+f"(c[3])
        : "r"(a0), "r"(a1), "r"(a2), "r"(a3), "r"(b0), "r"(b1));
}

__device__ __forceinline__ uint32_t smem_u32(const void* p) {
    return (uint32_t)__cvta_generic_to_shared(p);
}

__device__ __forceinline__ void ldsm4(uint32_t* r, uint32_t addr) {
    asm volatile("ldmatrix.sync.aligned.m8n8.x4.shared.b16 {%0,%1,%2,%3}, [%4];"
        : "=r"(r[0]), "=r"(r[1]), "=r"(r[2]), "=r"(r[3]) : "r"(addr));
}

__device__ __forceinline__ float sigf(float x) { return 1.f / (1.f + __expf(-x)); }
__device__ __forceinline__ float tanhfast(float x) {
    float ax = fminf(fmaxf(x, -15.f), 15.f);
    float e  = __expf(2.f * ax);
    return (e - 1.f) / (e + 1.f);
}

__device__ __forceinline__ void cpa16(void* dst, const void* src) {
    uint32_t s = smem_u32(dst);
    asm volatile("cp.async.cg.shared.global [%0], [%1], 16;\n" :: "r"(s), "l"(src));
}
__device__ __forceinline__ void cpa_commit() { asm volatile("cp.async.commit_group;\n"); }
template<int N> __device__ __forceinline__ void cpa_wait() {
    asm volatile("cp.async.wait_group %0;\n" :: "n"(N));
}

// ----------------- per-group barrier (two-hop: counter + clean phase line) -----------------
__device__ __forceinline__ void barg_wait(int* phs, int target) {
    if (threadIdx.x == 0) {
        int v;
        do {
            asm volatile("ld.acquire.gpu.global.s32 %0, [%1];" : "=r"(v) : "l"(phs) : "memory");
        } while (v < target);
    }
    __syncthreads();
}

// all-threads poll: X row-block rb (2 timesteps) complete when counter == 16
__device__ __forceinline__ void wait_x(int rb) {
    const int* f = &g_Xflag[rb*32];
    int v;
    do {
        asm volatile("ld.acquire.gpu.global.s32 %0, [%1];" : "=r"(v) : "l"(f) : "memory");
    } while (v < 16);
}

// ----------------- init -----------------
__global__ void k_init() {
    int i = blockIdx.x * blockDim.x + threadIdx.x;
    if (i < 2 * GRP * 16 * HID) ((__nv_bfloat16*)g_HG)[i] = __float2bfloat16(0.f);
    if (i < GRP*32) { g_cntG[i] = 0; g_phaseG[i] = 0; }
    if (i < 256*32) g_Xflag[i] = 0;
}

// ----------------- inputs -> split bf16 -----------------
__global__ void k_conv_in(const float* __restrict__ in) {
    size_t i = (size_t)blockIdx.x * blockDim.x + threadIdx.x;
    const size_t n4 = (size_t)TBM * DI / 4;
    if (i >= n4) return;
    float4 v = reinterpret_cast<const float4*>(in)[i];
    __nv_bfloat16 h0,h1,h2,h3,l0,l1,l2,l3;
    split_bf16(v.x, h0, l0); split_bf16(v.y, h1, l1);
    split_bf16(v.z, h2, l2); split_bf16(v.w, h3, l3);
    __nv_bfloat162* ph = reinterpret_cast<__nv_bfloat162*>(g_Ahi + 4*i);
    __nv_bfloat162* pl = reinterpret_cast<__nv_bfloat162*>(g_Alo + 4*i);
    ph[0] = __halves2bfloat162(h0, h1); ph[1] = __halves2bfloat162(h2, h3);
    pl[0] = __halves2bfloat162(l0, l1); pl[1] = __halves2bfloat162(l2, l3);
}

// ----------------- weights -> bf16, transposed, gate-interleaved c' = h*4+g -----------------
__global__ void k_conv_w(const float* __restrict__ Wxi, const float* __restrict__ Wxf,
                         const float* __restrict__ Wxo, const float* __restrict__ Wxc,
                         const float* __restrict__ Whi, const float* __restrict__ Whf,
                         const float* __restrict__ Who, const float* __restrict__ Whc,
                         const float* __restrict__ bi,  const float* __restrict__ bff,
                         const float* __restrict__ bo,  const float* __restrict__ bc) {
    const int NW = NG * DI;
    int stride = gridDim.x * blockDim.x;
    for (int i = blockIdx.x * blockDim.x + threadIdx.x; i < 2*NW + NG; i += stride) {
        if (i < NW) {                          // WxT[c'][d], split
            int c = i >> 9, d = i & 511;
            int h = c >> 2, gg = c & 3;
            const float* W = gg == 0 ? Wxi : (gg == 1 ? Wxf : (gg == 2 ? Wxo : Wxc));
            __nv_bfloat16 hi, lo; split_bf16(W[d*HID + h], hi, lo);
            g_WxThi[i] = hi; g_WxTlo[i] = lo;
        } else if (i < 2*NW) {                 // WhT[c'][k], hi only
            int jj = i - NW;
            int c = jj >> 9, k = jj & 511;
            int h = c >> 2, gg = c & 3;
            const float* W = gg == 0 ? Whi : (gg == 1 ? Whf : (gg == 2 ? Who : Whc));
            g_WhThi[jj] = __float2bfloat16(W[k*HID + h]);
        } else {                               // bias, c' order
            int c = i - 2*NW;
            int h = c >> 2, gg = c & 3;
            const float* bb = gg == 0 ? bi : (gg == 1 ? bff : (gg == 2 ? bo : bc));
            g_bias[c] = bb[h];
        }
    }
}

// ----------------- gemm tile (device fn; one 128x128 output tile) -----------------
__device__ __forceinline__ void gx_prefetch(__nv_bfloat16* smx, int ck, int s,
                                            int row0, int col0, int lr, int lh) {
    size_t gA = (size_t)(row0 + lr) * DI + ck*KCH + lh*8;
    size_t gB = (size_t)(col0 + lr) * DI + ck*KCH + lh*8;
    int so = lr*GPAD + lh*8;
    __nv_bfloat16* base = smx + (size_t)s*GSTG;
    cpa16(base + 0*GTILE + so, g_Ahi   + gA);
    cpa16(base + 1*GTILE + so, g_Alo   + gA);
    cpa16(base + 2*GTILE + so, g_WxThi + gB);
    cpa16(base + 3*GTILE + so, g_WxTlo + gB);
}

__device__ void gemm_tile(__nv_bfloat16* smx, int by, int bx) {
    const int tid = threadIdx.x, w = tid >> 5, l = tid & 31;
    const int wm = w & 3, wn = w >> 2, r = l >> 2, q = l & 3;
    const int row0 = by * 128, col0 = bx * 128;
    const int lr = tid >> 1, lh = tid & 1;
    const int grp = l >> 3, rr = l & 7;
    const int NK = DI / KCH;   // 32

    float acc[2][8][4];
    #pragma unroll
    for (int a = 0; a < 2; a++)
        #pragma unroll
        for (int b = 0; b < 8; b++)
            #pragma unroll
            for (int c = 0; c < 4; c++) acc[a][b][c] = 0.f;

    gx_prefetch(smx, 0, 0, row0, col0, lr, lh);
    cpa_commit();
    gx_prefetch(smx, 1, 1, row0, col0, lr, lh);
    cpa_commit();

    for (int ck = 0; ck < NK; ck++) {
        cpa_wait<1>();
        __syncthreads();

        if (ck + 2 < NK) {
            gx_prefetch(smx, ck + 2, (ck + 2) % 3, row0, col0, lr, lh);
            cpa_commit();
        } else {
            cpa_commit();
        }

        const __nv_bfloat16* base = smx + (size_t)(ck % 3)*GSTG;
        const __nv_bfloat16* Ah_s = base + 0*GTILE;
        const __nv_bfloat16* Al_s = base + 1*GTILE;
        const __nv_bfloat16* Bh_s = base + 2*GTILE;
        const __nv_bfloat16* Bl_s = base + 3*GTILE;

        const int acol = (grp >> 1)*8;
        uint32_t Ahf[2][4], Alf[2][4];
        #pragma unroll
        for (int mt = 0; mt < 2; mt++) {
            int arow = wm*32 + mt*16 + (grp & 1)*8 + rr;
            ldsm4(Ahf[mt], smem_u32(&Ah_s[arow*GPAD + acol]));
            ldsm4(Alf[mt], smem_u32(&Al_s[arow*GPAD + acol]));
        }
        #pragma unroll
        for (int np = 0; np < 4; np++) {
            int brow = wn*64 + np*16 + (grp >> 1)*8 + rr;
            int bcol = (grp & 1)*8;
            uint32_t bh[4], bl[4];
            ldsm4(bh, smem_u32(&Bh_s[brow*GPAD + bcol]));
            ldsm4(bl, smem_u32(&Bl_s[brow*GPAD + bcol]));
            #pragma unroll
            for (int mt = 0; mt < 2; mt++) {
                float* a0 = acc[mt][np*2];
                float* a1 = acc[mt][np*2 + 1];
                mma16816(a0, Ahf[mt][0], Ahf[mt][1], Ahf[mt][2], Ahf[mt][3], bh[0], bh[1]);
                mma16816(a0, Alf[mt][0], Alf[mt][1], Alf[mt][2], Alf[mt][3], bh[0], bh[1]);
                mma16816(a0, Ahf[mt][0], Ahf[mt][1], Ahf[mt][2], Ahf[mt][3], bl[0], bl[1]);
                mma16816(a1, Ahf[mt][0], Ahf[mt][1], Ahf[mt][2], Ahf[mt][3], bh[2], bh[3]);
                mma16816(a1, Alf[mt][0], Alf[mt][1], Alf[mt][2], Alf[mt][3], bh[2], bh[3]);
                mma16816(a1, Ahf[mt][0], Ahf[mt][1], Ahf[mt][2], Ahf[mt][3], bl[2], bl[3]);
            }
        }
    }

    #pragma unroll
    for (int mt = 0; mt < 2; mt++) {
        #pragma unroll
        for (int nt = 0; nt < 8; nt++) {
            int grow = row0 + wm*32 + mt*16 + r;
            int gcol = col0 + wn*64 + nt*8 + 2*q;
            float2 bb = *(const float2*)&g_bias[gcol];
            float2 v0 = make_float2(acc[mt][nt][0] + bb.x, acc[mt][nt][1] + bb.y);
            float2 v1 = make_float2(acc[mt][nt][2] + bb.x, acc[mt][nt][3] + bb.y);
            *(float2*)&g_X[(size_t)grow * NG + gcol]       = v0;
            *(float2*)&g_X[(size_t)(grow + 8) * NG + gcol] = v1;
        }
    }

    // publish: row-block by ready when all 16 col blocks arrive
    __syncthreads();
    if (threadIdx.x == 0) {
        asm volatile("red.release.gpu.global.add.s32 [%0], %1;"
                     :: "l"(&g_Xflag[by*32]), "r"(1) : "memory");
    }
    // drain committed cp.asyncs before smem reuse on next tile
    cpa_wait<0>();
    __syncthreads();
}

// ----------------- lstm role (device fn) -----------------
__device__ void lstm_body(float* __restrict__ out, char* dynsm, int blk) {
    __nv_bfloat16* sH   = (__nv_bfloat16*)dynsm;           // 16KB H copy
    __nv_bfloat16* sOut = (__nv_bfloat16*)(dynsm + 16384); // 512B publish staging

    const int tid = threadIdx.x, w = tid >> 5, l = tid & 31;
    const int r = l >> 2, q = l & 3;
    const int g = blk >> 5, j = blk & 31;
    int* cnt = &g_cntG[g*32];
    int* phs = &g_phaseG[g*32];

    // Wh-hi fragments in registers: warp's col = j*64 + w*8 + r, all 32 k-frags
    uint32_t Bh[32][2];
    {
        const __nv_bfloat16* wp = g_WhThi + (size_t)(j*64 + w*8 + r) * HID;
        #pragma unroll
        for (int ktl = 0; ktl < 32; ktl++) {
            int kg = ktl * 16;
            Bh[ktl][0] = *(const uint32_t*)(wp + kg + 2*q);
            Bh[ktl][1] = *(const uint32_t*)(wp + kg + 2*q + 8);
        }
    }

    float C = 0.f;
    const int myrow = (q & 1) ? (r + 8) : r;
    const int hid   = j*16 + w*2 + (q >> 1);
    const int kk    = hid & 15;
    const int plane = ((myrow & 7) << 2) | ((kk & 7) >> 1);
    const int preg  = ((myrow >> 3) & 1) | ((kk >> 3) << 1);
    const int sloc  = plane*8 + preg*2 + (kk & 1);   // offset within block's 256-elem H region
    const int c0    = j*64 + w*8 + 2*q;

    // wait for X row-block 0, then prefetch t=0 seeds
    wait_x(0);
    float2 sd01, sd23;
    {
        size_t row0 = (size_t)(g*16 + r);
        sd01 = __ldcg((const float2*)&g_X[row0 * NG + c0]);
        sd23 = __ldcg((const float2*)&g_X[(row0 + 8) * NG + c0]);
    }

    for (int t = 0; t < TS; t++) {
        const int rb = t & 1;
        float acc[4], acc2[4];
        acc[0] = sd01.x; acc[1] = sd01.y; acc[2] = sd23.x; acc[3] = sd23.y;
        acc2[0] = acc2[1] = acc2[2] = acc2[3] = 0.f;

        if (t > 0) barg_wait(phs, t);   // group's H(t-1) visible

        // chunked cooperative H copy: 2 x 8KB via cp.async
        const __nv_bfloat16* Hg = g_HG[rb][g];
        cpa16(sH + (size_t)tid*8,         Hg + (size_t)tid*8);
        cpa16(sH + (size_t)(tid+256)*8,   Hg + (size_t)(tid+256)*8);
        cpa_commit();
        cpa16(sH + (size_t)(tid+512)*8,   Hg + (size_t)(tid+512)*8);
        cpa16(sH + (size_t)(tid+768)*8,   Hg + (size_t)(tid+768)*8);
        cpa_commit();

        // prefetch seeds for t+1 (new X row-block every 2 steps; poll its flag)
        if (t + 1 < TS) {
            if (((t + 1) & 1) == 0) wait_x((t + 1) >> 1);
            size_t rown = (size_t)((t + 1)*BA + g*16 + r);
            sd01 = __ldcg((const float2*)&g_X[rown * NG + c0]);
            sd23 = __ldcg((const float2*)&g_X[(rown + 8) * NG + c0]);
        }

        cpa_wait<1>();
        __syncthreads();
        #pragma unroll
        for (int ktl = 0; ktl < 16; ktl += 2) {
            uint4 a0 = *(const uint4*)(sH + (size_t)(ktl*32 + l)*8);
            uint4 a1 = *(const uint4*)(sH + (size_t)((ktl + 1)*32 + l)*8);
            mma16816(acc,  a0.x, a0.y, a0.z, a0.w, Bh[ktl][0],   Bh[ktl][1]);
            mma16816(acc2, a1.x, a1.y, a1.z, a1.w, Bh[ktl+1][0], Bh[ktl+1][1]);
        }
        cpa_wait<0>();
        __syncthreads();
        #pragma unroll
        for (int ktl = 16; ktl < 32; ktl += 2) {
            uint4 a0 = *(const uint4*)(sH + (size_t)(ktl*32 + l)*8);
            uint4 a1 = *(const uint4*)(sH + (size_t)((ktl + 1)*32 + l)*8);
            mma16816(acc,  a0.x, a0.y, a0.z, a0.w, Bh[ktl][0],   Bh[ktl][1]);
            mma16816(acc2, a1.x, a1.y, a1.z, a1.w, Bh[ktl+1][0], Bh[ktl+1][1]);
        }
        acc[0] += acc2[0]; acc[1] += acc2[1]; acc[2] += acc2[2]; acc[3] += acc2[3];

        // gather 4 gates into one thread via lane-pair shuffle
        float s0 = __shfl_xor_sync(0xffffffffu, acc[0], 1);
        float s1 = __shfl_xor_sync(0xffffffffu, acc[1], 1);
        float s2 = __shfl_xor_sync(0xffffffffu, acc[2], 1);
        float s3 = __shfl_xor_sync(0xffffffffu, acc[3], 1);
        float xi, xf, xo, xc;
        if (q & 1) { xi = s2;     xf = s3;     xo = acc[2]; xc = acc[3]; }
        else       { xi = acc[0]; xf = acc[1]; xo = s0;     xc = s1;     }

        float I  = sigf(xi), F = sigf(xf), O = sigf(xo);
        float Ct = tanhfast(xc);
        C = F*C + I*Ct;
        float Hn = O * tanhfast(C);

        // stage H in smem, publish coalesced from warp 0, then release
        sOut[sloc] = __float2bfloat16(Hn);
        __syncthreads();   // orders: sOut writes, MMA reads of sH (reuse), all pre-publish work
        if (tid < 32) {
            uint4 v = *(const uint4*)(sOut + tid*8);
            __nv_bfloat16* dst = &g_HG[rb ^ 1][g][j*256 + tid*8];
            asm volatile("st.global.cg.v4.u32 [%0], {%1,%2,%3,%4};"
                         :: "l"(dst), "r"(v.x), "r"(v.y), "r"(v.z), "r"(v.w) : "memory");
            __syncwarp();
            if (tid == 0) {
                int old;
                asm volatile("atom.release.gpu.global.add.s32 %0, [%1], %2;"
                             : "=r"(old) : "l"(cnt), "r"(1) : "memory");
                if (old == BPG - 1) {
                    asm volatile("st.relaxed.gpu.global.s32 [%0], %1;" :: "l"(cnt), "r"(0) : "memory");
                    asm volatile("st.release.gpu.global.s32 [%0], %1;" :: "l"(phs), "r"(t + 1) : "memory");
                }
            }
        }

        // off the critical path: fp32 outputs
        int batch = g*16 + myrow;
        out[((size_t)t*BA + batch)*HID + hid] = Hn;
        if (t == TS - 1) {
            out[(size_t)TS*BA*HID + (size_t)batch*HID + hid]                  = Hn;
            out[(size_t)TS*BA*HID + (size_t)BA*HID + (size_t)batch*HID + hid] = C;
        }
    }
}

// ----------------- fused kernel: lstm blocks 0..127, gemm workers 128..295 -----------------
__global__ __launch_bounds__(256, 2) void k_fused(float* __restrict__ out) {
    extern __shared__ char dynsm[];
    const int bid = blockIdx.x;
    if (bid < NLSTM) {
        lstm_body(out, dynsm, bid);
    } else {
        const int wkr = bid - NLSTM;
        __nv_bfloat16* smx = (__nv_bfloat16*)dynsm;
        for (int tile = wkr; tile < 256*16; tile += NWKR) {
            gemm_tile(smx, tile >> 4, tile & 15);
        }
    }
}

// ----------------- launch -----------------
extern "C" void kernel_launch(void* const* d_in, const int* in_sizes, int n_in,
                              void* d_out, int out_size) {
    const float* inp = (const float*)d_in[0];
    const float* Wxi = (const float*)d_in[1];
    const float* Whi = (const float*)d_in[2];
    const float* bi  = (const float*)d_in[3];
    const float* Wxf = (const float*)d_in[4];
    const float* Whf = (const float*)d_in[5];
    const float* bf  = (const float*)d_in[6];
    const float* Wxo = (const float*)d_in[7];
    const float* Who = (const float*)d_in[8];
    const float* bo  = (const float*)d_in[9];
    const float* Wxc = (const float*)d_in[10];
    const float* Whc = (const float*)d_in[11];
    const float* bc  = (const float*)d_in[12];
    float* out = (float*)d_out;

    static int inited = 0;
    if (!inited) {
        cudaFuncSetAttribute(k_fused, cudaFuncAttributeMaxDynamicSharedMemorySize, GSMEM);
        inited = 1;
    }

    k_init<<<256, 256>>>();
    k_conv_in<<<16384, 256>>>(inp);
    k_conv_w<<<2048, 256>>>(Wxi, Wxf, Wxo, Wxc, Whi, Whf, Who, Whc, bi, bf, bo, bc);
    k_fused<<<NLSTM + NWKR, 256, GSMEM>>>(out);
}

// round 16
// speedup vs baseline: 1.1801x; 1.0141x over previous
#include <cuda_runtime.h>
#include <cuda_bf16.h>
#include <stdint.h>

#define TS   512
#define BA   64
#define DI   512
#define HID  512
#define NG   2048          // 4 gates * HID, INTERLEAVED: c' = hid*4 + gate (0=i,1=f,2=o,3=c)
#define TBM  (TS*BA)
#define GRP  4             // independent batch groups
#define BPG  32            // blocks per group
#define NLSTM 128          // lstm blocks (bids 0..127)
#define NWKR  168          // gemm worker blocks (bids 128..295)

// gemm pipeline: k-chunk 16, pad rows to 24 elems, 3 stages, 4 arrays (Ahi, Alo, Wxhi, Wxlo)
#define KCH   16
#define GPAD  24
#define GTILE (128*GPAD)               // elems per array per stage (3072)
#define GSTG  (4*GTILE)                // elems per stage (4 arrays)
#define GSMEM (3*GSTG*2)               // bytes total (73728)

// ----------------- device-global scratch -----------------
static __device__ __align__(16) __nv_bfloat16 g_Ahi[(size_t)TBM*DI];
static __device__ __align__(16) __nv_bfloat16 g_Alo[(size_t)TBM*DI];
static __device__ __align__(16) __nv_bfloat16 g_WxThi[(size_t)NG*DI];   // [c'][d], K-major
static __device__ __align__(16) __nv_bfloat16 g_WxTlo[(size_t)NG*DI];
static __device__ __align__(16) __nv_bfloat16 g_WhThi[(size_t)NG*HID];  // [c'][k], K-major
static __device__ __align__(16) float         g_bias[NG];               // c' order
static __device__ __align__(16) float         g_X[(size_t)TBM*NG];      // c' order
static __device__ __align__(16) __nv_bfloat16 g_HG[2][GRP][16*HID];     // per-group H, frag order
static __device__ int g_cntG[GRP*32];      // padded arrival counters
static __device__ int g_phaseG[GRP*32];    // padded phase flags
static __device__ int g_Xflag[256*32];     // per-row-block (2 timesteps) counters, padded

// ----------------- helpers -----------------
__device__ __forceinline__ void split_bf16(float v, __nv_bfloat16& hi, __nv_bfloat16& lo) {
    hi = __float2bfloat16(v);
    lo = __float2bfloat16(v - __bfloat162float(hi));
}

__device__ __forceinline__ void mma16816(float* c,
                                         uint32_t a0, uint32_t a1, uint32_t a2, uint32_t a3,
                                         uint32_t b0, uint32_t b1) {
    asm volatile(
        "mma.sync.aligned.m16n8k16.row.col.f32.bf16.bf16.f32 "
        "{%0,%1,%2,%3},{%4,%5,%6,%7},{%8,%9},{%0,%1,%2,%3};\n"
        : "+f"(c[0]), "+f"(c[1]), "+f"(c[2]), "+f"(c[3])
        : "r"(a0), "r"(a1), "r"(a2), "r"(a3), "r"(b0), "r"(b1));
}

__device__ __forceinline__ uint32_t smem_u32(const void* p) {
    return (uint32_t)__cvta_generic_to_shared(p);
}

__device__ __forceinline__ void ldsm4(uint32_t* r, uint32_t addr) {
    asm volatile("ldmatrix.sync.aligned.m8n8.x4.shared.b16 {%0,%1,%2,%3}, [%4];"
        : "=r"(r[0]), "=r"(r[1]), "=r"(r[2]), "=r"(r[3]) : "r"(addr));
}

__device__ __forceinline__ float sigf(float x) { return 1.f / (1.f + __expf(-x)); }
__device__ __forceinline__ float tanhfast(float x) {
    float ax = fminf(fmaxf(x, -15.f), 15.f);
    float e  = __expf(2.f * ax);
    return (e - 1.f) / (e + 1.f);
}

__device__ __forceinline__ void cpa16(void* dst, const void* src) {
    uint32_t s = smem_u32(dst);
    asm volatile("cp.async.cg.shared.global [%0], [%1], 16;\n" :: "r"(s), "l"(src));
}
__device__ __forceinline__ void cpa_commit() { asm volatile("cp.async.commit_group;\n"); }
template<int N> __device__ __forceinline__ void cpa_wait() {
    asm volatile("cp.async.wait_group %0;\n" :: "n"(N));
}

// ----------------- per-group barrier (two-hop: counter + clean phase line) -----------------
__device__ __forceinline__ void barg_wait(int* phs, int target) {
    if (threadIdx.x == 0) {
        int v;
        do {
            asm volatile("ld.acquire.gpu.global.s32 %0, [%1];" : "=r"(v) : "l"(phs) : "memory");
        } while (v < target);
    }
    __syncthreads();
}

// all-threads poll: X row-block rb (2 timesteps) complete when counter == 16
__device__ __forceinline__ void wait_x(int rb) {
    const int* f = &g_Xflag[rb*32];
    int v;
    do {
        asm volatile("ld.acquire.gpu.global.s32 %0, [%1];" : "=r"(v) : "l"(f) : "memory");
    } while (v < 16);
}

// ----------------- init -----------------
__global__ void k_init() {
    int i = blockIdx.x * blockDim.x + threadIdx.x;
    if (i < 2 * GRP * 16 * HID) ((__nv_bfloat16*)g_HG)[i] = __float2bfloat16(0.f);
    if (i < GRP*32) { g_cntG[i] = 0; g_phaseG[i] = 0; }
    if (i < 256*32) g_Xflag[i] = 0;
}

// ----------------- inputs -> split bf16 -----------------
__global__ void k_conv_in(const float* __restrict__ in) {
    size_t i = (size_t)blockIdx.x * blockDim.x + threadIdx.x;
    const size_t n4 = (size_t)TBM * DI / 4;
    if (i >= n4) return;
    float4 v = reinterpret_cast<const float4*>(in)[i];
    __nv_bfloat16 h0,h1,h2,h3,l0,l1,l2,l3;
    split_bf16(v.x, h0, l0); split_bf16(v.y, h1, l1);
    split_bf16(v.z, h2, l2); split_bf16(v.w, h3, l3);
    __nv_bfloat162* ph = reinterpret_cast<__nv_bfloat162*>(g_Ahi + 4*i);
    __nv_bfloat162* pl = reinterpret_cast<__nv_bfloat162*>(g_Alo + 4*i);
    ph[0] = __halves2bfloat162(h0, h1); ph[1] = __halves2bfloat162(h2, h3);
    pl[0] = __halves2bfloat162(l0, l1); pl[1] = __halves2bfloat162(l2, l3);
}

// ----------------- weights -> bf16, transposed, gate-interleaved c' = h*4+g -----------------
__global__ void k_conv_w(const float* __restrict__ Wxi, const float* __restrict__ Wxf,
                         const float* __restrict__ Wxo, const float* __restrict__ Wxc,
                         const float* __restrict__ Whi, const float* __restrict__ Whf,
                         const float* __restrict__ Who, const float* __restrict__ Whc,
                         const float* __restrict__ bi,  const float* __restrict__ bff,
                         const float* __restrict__ bo,  const float* __restrict__ bc) {
    const int NW = NG * DI;
    int stride = gridDim.x * blockDim.x;
    for (int i = blockIdx.x * blockDim.x + threadIdx.x; i < 2*NW + NG; i += stride) {
        if (i < NW) {                          // WxT[c'][d], split
            int c = i >> 9, d = i & 511;
            int h = c >> 2, gg = c & 3;
            const float* W = gg == 0 ? Wxi : (gg == 1 ? Wxf : (gg == 2 ? Wxo : Wxc));
            __nv_bfloat16 hi, lo; split_bf16(W[d*HID + h], hi, lo);
            g_WxThi[i] = hi; g_WxTlo[i] = lo;
        } else if (i < 2*NW) {                 // WhT[c'][k], hi only
            int jj = i - NW;
            int c = jj >> 9, k = jj & 511;
            int h = c >> 2, gg = c & 3;
            const float* W = gg == 0 ? Whi : (gg == 1 ? Whf : (gg == 2 ? Who : Whc));
            g_WhThi[jj] = __float2bfloat16(W[k*HID + h]);
        } else {                               // bias, c' order
            int c = i - 2*NW;
            int h = c >> 2, gg = c & 3;
            const float* bb = gg == 0 ? bi : (gg == 1 ? bff : (gg == 2 ? bo : bc));
            g_bias[c] = bb[h];
        }
    }
}

// ----------------- gemm tile (device fn; one 128x128 output tile; 3-term split) -----------------
__device__ __forceinline__ void gx_prefetch(__nv_bfloat16* smx, int ck, int s,
                                            int row0, int col0, int lr, int lh) {
    size_t gA = (size_t)(row0 + lr) * DI + ck*KCH + lh*8;
    size_t gB = (size_t)(col0 + lr) * DI + ck*KCH + lh*8;
    int so = lr*GPAD + lh*8;
    __nv_bfloat16* base = smx + (size_t)s*GSTG;
    cpa16(base + 0*GTILE + so, g_Ahi   + gA);
    cpa16(base + 1*GTILE + so, g_Alo   + gA);
    cpa16(base + 2*GTILE + so, g_WxThi + gB);
    cpa16(base + 3*GTILE + so, g_WxTlo + gB);
}

__device__ void gemm_tile(__nv_bfloat16* smx, int by, int bx) {
    const int tid = threadIdx.x, w = tid >> 5, l = tid & 31;
    const int wm = w & 3, wn = w >> 2, r = l >> 2, q = l & 3;
    const int row0 = by * 128, col0 = bx * 128;
    const int lr = tid >> 1, lh = tid & 1;
    const int grp = l >> 3, rr = l & 7;
    const int NK = DI / KCH;   // 32

    float acc[2][8][4];
    #pragma unroll
    for (int a = 0; a < 2; a++)
        #pragma unroll
        for (int b = 0; b < 8; b++)
            #pragma unroll
            for (int c = 0; c < 4; c++) acc[a][b][c] = 0.f;

    gx_prefetch(smx, 0, 0, row0, col0, lr, lh);
    cpa_commit();
    gx_prefetch(smx, 1, 1, row0, col0, lr, lh);
    cpa_commit();

    for (int ck = 0; ck < NK; ck++) {
        cpa_wait<1>();
        __syncthreads();

        if (ck + 2 < NK) {
            gx_prefetch(smx, ck + 2, (ck + 2) % 3, row0, col0, lr, lh);
            cpa_commit();
        } else {
            cpa_commit();
        }

        const __nv_bfloat16* base = smx + (size_t)(ck % 3)*GSTG;
        const __nv_bfloat16* Ah_s = base + 0*GTILE;
        const __nv_bfloat16* Al_s = base + 1*GTILE;
        const __nv_bfloat16* Bh_s = base + 2*GTILE;
        const __nv_bfloat16* Bl_s = base + 3*GTILE;

        const int acol = (grp >> 1)*8;
        uint32_t Ahf[2][4], Alf[2][4];
        #pragma unroll
        for (int mt = 0; mt < 2; mt++) {
            int arow = wm*32 + mt*16 + (grp & 1)*8 + rr;
            ldsm4(Ahf[mt], smem_u32(&Ah_s[arow*GPAD + acol]));
            ldsm4(Alf[mt], smem_u32(&Al_s[arow*GPAD + acol]));
        }
        #pragma unroll
        for (int np = 0; np < 4; np++) {
            int brow = wn*64 + np*16 + (grp >> 1)*8 + rr;
            int bcol = (grp & 1)*8;
            uint32_t bh[4], bl[4];
            ldsm4(bh, smem_u32(&Bh_s[brow*GPAD + bcol]));
            ldsm4(bl, smem_u32(&Bl_s[brow*GPAD + bcol]));
            #pragma unroll
            for (int mt = 0; mt < 2; mt++) {
                float* a0 = acc[mt][np*2];
                float* a1 = acc[mt][np*2 + 1];
                mma16816(a0, Ahf[mt][0], Ahf[mt][1], Ahf[mt][2], Ahf[mt][3], bh[0], bh[1]);
                mma16816(a0, Alf[mt][0], Alf[mt][1], Alf[mt][2], Alf[mt][3], bh[0], bh[1]);
                mma16816(a0, Ahf[mt][0], Ahf[mt][1], Ahf[mt][2], Ahf[mt][3], bl[0], bl[1]);
                mma16816(a1, Ahf[mt][0], Ahf[mt][1], Ahf[mt][2], Ahf[mt][3], bh[2], bh[3]);
                mma16816(a1, Alf[mt][0], Alf[mt][1], Alf[mt][2], Alf[mt][3], bh[2], bh[3]);
                mma16816(a1, Ahf[mt][0], Ahf[mt][1], Ahf[mt][2], Ahf[mt][3], bl[2], bl[3]);
            }
        }
    }

    #pragma unroll
    for (int mt = 0; mt < 2; mt++) {
        #pragma unroll
        for (int nt = 0; nt < 8; nt++) {
            int grow = row0 + wm*32 + mt*16 + r;
            int gcol = col0 + wn*64 + nt*8 + 2*q;
            float2 bb = *(const float2*)&g_bias[gcol];
            float2 v0 = make_float2(acc[mt][nt][0] + bb.x, acc[mt][nt][1] + bb.y);
            float2 v1 = make_float2(acc[mt][nt][2] + bb.x, acc[mt][nt][3] + bb.y);
            *(float2*)&g_X[(size_t)grow * NG + gcol]       = v0;
            *(float2*)&g_X[(size_t)(grow + 8) * NG + gcol] = v1;
        }
    }

    // publish: row-block by ready when all 16 col blocks arrive
    __syncthreads();
    if (threadIdx.x == 0) {
        asm volatile("red.release.gpu.global.add.s32 [%0], %1;"
                     :: "l"(&g_Xflag[by*32]), "r"(1) : "memory");
    }
    // drain committed cp.asyncs before smem reuse on next tile
    cpa_wait<0>();
    __syncthreads();
}

// ----------------- lstm role (device fn) -----------------
__device__ void lstm_body(float* __restrict__ out, char* dynsm, int blk) {
    __nv_bfloat16* sH    = (__nv_bfloat16*)dynsm;            // 16KB H copy
    __nv_bfloat16* sOut  = (__nv_bfloat16*)(dynsm + 16384);  // 512B H publish staging
    float*         sOutF = (float*)(dynsm + 16896);          // 1KB fp32 out staging

    const int tid = threadIdx.x, w = tid >> 5, l = tid & 31;
    const int r = l >> 2, q = l & 3;
    const int g = blk >> 5, j = blk & 31;
    int* cnt = &g_cntG[g*32];
    int* phs = &g_phaseG[g*32];

    // Wh-hi fragments in registers: warp's col = j*64 + w*8 + r, all 32 k-frags
    uint32_t Bh[32][2];
    {
        const __nv_bfloat16* wp = g_WhThi + (size_t)(j*64 + w*8 + r) * HID;
        #pragma unroll
        for (int ktl = 0; ktl < 32; ktl++) {
            int kg = ktl * 16;
            Bh[ktl][0] = *(const uint32_t*)(wp + kg + 2*q);
            Bh[ktl][1] = *(const uint32_t*)(wp + kg + 2*q + 8);
        }
    }

    float C = 0.f;
    const int myrow = (q & 1) ? (r + 8) : r;
    const int hid   = j*16 + w*2 + (q >> 1);
    const int col   = w*2 + (q >> 1);                // local hid col 0..15
    const int kk    = hid & 15;
    const int plane = ((myrow & 7) << 2) | ((kk & 7) >> 1);
    const int preg  = ((myrow >> 3) & 1) | ((kk >> 3) << 1);
    const int sloc  = plane*8 + preg*2 + (kk & 1);   // offset within block's 256-elem H region
    const int c0    = j*64 + w*8 + 2*q;

    // wait for X row-block 0, then prefetch t=0 seeds
    wait_x(0);
    float2 sd01, sd23;
    {
        size_t row0 = (size_t)(g*16 + r);
        sd01 = __ldcg((const float2*)&g_X[row0 * NG + c0]);
        sd23 = __ldcg((const float2*)&g_X[(row0 + 8) * NG + c0]);
    }

    for (int t = 0; t < TS; t++) {
        const int rb = t & 1;
        float acc[4], acc2[4];
        acc[0] = sd01.x; acc[1] = sd01.y; acc[2] = sd23.x; acc[3] = sd23.y;
        acc2[0] = acc2[1] = acc2[2] = acc2[3] = 0.f;

        if (t > 0) barg_wait(phs, t);   // group's H(t-1) visible

        // chunked cooperative H copy: 2 x 8KB via cp.async
        const __nv_bfloat16* Hg = g_HG[rb][g];
        cpa16(sH + (size_t)tid*8,         Hg + (size_t)tid*8);
        cpa16(sH + (size_t)(tid+256)*8,   Hg + (size_t)(tid+256)*8);
        cpa_commit();
        cpa16(sH + (size_t)(tid+512)*8,   Hg + (size_t)(tid+512)*8);
        cpa16(sH + (size_t)(tid+768)*8,   Hg + (size_t)(tid+768)*8);
        cpa_commit();

        // prefetch seeds for t+1 (new X row-block every 2 steps; poll its flag)
        if (t + 1 < TS) {
            if (((t + 1) & 1) == 0) wait_x((t + 1) >> 1);
            size_t rown = (size_t)((t + 1)*BA + g*16 + r);
            sd01 = __ldcg((const float2*)&g_X[rown * NG + c0]);
            sd23 = __ldcg((const float2*)&g_X[(rown + 8) * NG + c0]);
        }

        cpa_wait<1>();
        __syncthreads();
        #pragma unroll
        for (int ktl = 0; ktl < 16; ktl += 2) {
            uint4 a0 = *(const uint4*)(sH + (size_t)(ktl*32 + l)*8);
            uint4 a1 = *(const uint4*)(sH + (size_t)((ktl + 1)*32 + l)*8);
            mma16816(acc,  a0.x, a0.y, a0.z, a0.w, Bh[ktl][0],   Bh[ktl][1]);
            mma16816(acc2, a1.x, a1.y, a1.z, a1.w, Bh[ktl+1][0], Bh[ktl+1][1]);
        }
        cpa_wait<0>();
        __syncthreads();
        #pragma unroll
        for (int ktl = 16; ktl < 32; ktl += 2) {
            uint4 a0 = *(const uint4*)(sH + (size_t)(ktl*32 + l)*8);
            uint4 a1 = *(const uint4*)(sH + (size_t)((ktl + 1)*32 + l)*8);
            mma16816(acc,  a0.x, a0.y, a0.z, a0.w, Bh[ktl][0],   Bh[ktl][1]);
            mma16816(acc2, a1.x, a1.y, a1.z, a1.w, Bh[ktl+1][0], Bh[ktl+1][1]);
        }
        acc[0] += acc2[0]; acc[1] += acc2[1]; acc[2] += acc2[2]; acc[3] += acc2[3];

        // gather 4 gates into one thread via lane-pair shuffle
        float s0 = __shfl_xor_sync(0xffffffffu, acc[0], 1);
        float s1 = __shfl_xor_sync(0xffffffffu, acc[1], 1);
        float s2 = __shfl_xor_sync(0xffffffffu, acc[2], 1);
        float s3 = __shfl_xor_sync(0xffffffffu, acc[3], 1);
        float xi, xf, xo, xc;
        if (q & 1) { xi = s2;     xf = s3;     xo = acc[2]; xc = acc[3]; }
        else       { xi = acc[0]; xf = acc[1]; xo = s0;     xc = s1;     }

        float I  = sigf(xi), F = sigf(xf), O = sigf(xo);
        float Ct = tanhfast(xc);
        C = F*C + I*Ct;
        float Hn = O * tanhfast(C);

        // stage H (bf16, frag order) + fp32 out tile in smem
        sOut[sloc] = __float2bfloat16(Hn);
        sOutF[myrow*16 + col] = Hn;
        __syncthreads();   // orders: sOut/sOutF writes, sH reuse, all pre-publish work
        if (tid < 32) {
            uint4 v = *(const uint4*)(sOut + tid*8);
            __nv_bfloat16* dst = &g_HG[rb ^ 1][g][j*256 + tid*8];
            asm volatile("st.global.cg.v4.u32 [%0], {%1,%2,%3,%4};"
                         :: "l"(dst), "r"(v.x), "r"(v.y), "r"(v.z), "r"(v.w) : "memory");
            __syncwarp();
            if (tid == 0) {
                int old;
                asm volatile("atom.release.gpu.global.add.s32 %0, [%1], %2;"
                             : "=r"(old) : "l"(cnt), "r"(1) : "memory");
                if (old == BPG - 1) {
                    asm volatile("st.relaxed.gpu.global.s32 [%0], %1;" :: "l"(cnt), "r"(0) : "memory");
                    asm volatile("st.release.gpu.global.s32 [%0], %1;" :: "l"(phs), "r"(t + 1) : "memory");
                }
            }
        }

        // off the critical path: coalesced fp32 outputs (16 threads = 64B run)
        {
            int orow = tid >> 4, ocol = tid & 15;
            out[((size_t)t*BA + g*16 + orow)*HID + j*16 + ocol] = sOutF[tid];
        }
        if (t == TS - 1) {
            int batch = g*16 + myrow;
            out[(size_t)TS*BA*HID + (size_t)batch*HID + hid]                  = Hn;
            out[(size_t)TS*BA*HID + (size_t)BA*HID + (size_t)batch*HID + hid] = C;
        }
    }
}

// ----------------- fused kernel: lstm blocks 0..127, gemm workers 128..295 -----------------
__global__ __launch_bounds__(256, 2) void k_fused(float* __restrict__ out) {
    extern __shared__ char dynsm[];
    const int bid = blockIdx.x;
    if (bid < NLSTM) {
        lstm_body(out, dynsm, bid);
    } else {
        const int wkr = bid - NLSTM;
        __nv_bfloat16* smx = (__nv_bfloat16*)dynsm;
        for (int tile = wkr; tile < 256*16; tile += NWKR) {
            gemm_tile(smx, tile >> 4, tile & 15);
        }
    }
}

// ----------------- launch -----------------
extern "C" void kernel_launch(void* const* d_in, const int* in_sizes, int n_in,
                              void* d_out, int out_size) {
    const float* inp = (const float*)d_in[0];
    const float* Wxi = (const float*)d_in[1];
    const float* Whi = (const float*)d_in[2];
    const float* bi  = (const float*)d_in[3];
    const float* Wxf = (const float*)d_in[4];
    const float* Whf = (const float*)d_in[5];
    const float* bf  = (const float*)d_in[6];
    const float* Wxo = (const float*)d_in[7];
    const float* Who = (const float*)d_in[8];
    const float* bo  = (const float*)d_in[9];
    const float* Wxc = (const float*)d_in[10];
    const float* Whc = (const float*)d_in[11];
    const float* bc  = (const float*)d_in[12];
    float* out = (float*)d_out;

    static int inited = 0;
    if (!inited) {
        cudaFuncSetAttribute(k_fused, cudaFuncAttributeMaxDynamicSharedMemorySize, GSMEM);
        inited = 1;
    }

    k_init<<<256, 256>>>();
    k_conv_in<<<16384, 256>>>(inp);
    k_conv_w<<<2048, 256>>>(Wxi, Wxf, Wxo, Wxc, Whi, Whf, Who, Whc, bi, bf, bo, bc);
    k_fused<<<NLSTM + NWKR, 256, GSMEM>>>(out);
}

// round 17
// speedup vs baseline: 1.2265x; 1.0394x over previous
#include <cuda_runtime.h>
#include <cuda_fp16.h>
#include <stdint.h>

#define TS   512
#define BA   64
#define DI   512
#define HID  512
#define NG   2048          // 4 gates * HID, INTERLEAVED: c' = hid*4 + gate (0=i,1=f,2=o,3=c)
#define TBM  (TS*BA)
#define GRP  4             // independent batch groups
#define BPG  32            // blocks per group
#define NLSTM 128          // lstm blocks (bids 0..127)
#define NWKR  168          // gemm worker blocks (bids 128..295)
#define WSCALE 1024.0f     // Wx scaling (power of 2; epilogue multiplies by 1/WSCALE)

// gemm pipeline: k-chunk 16, pad rows to 24 elems, 3 stages, 3 arrays (A, Wxhi, Wxlo)
#define KCH   16
#define GPAD  24
#define GTILE (128*GPAD)               // elems per array per stage (3072)
#define GSTG  (3*GTILE)                // elems per stage (3 arrays)
#define GSMEM (3*GSTG*2)               // bytes total (55296)

// ----------------- device-global scratch -----------------
static __device__ __align__(16) __half g_A[(size_t)TBM*DI];           // inputs, fp16
static __device__ __align__(16) __half g_WxThi[(size_t)NG*DI];        // [c'][d], K-major, x1024
static __device__ __align__(16) __half g_WxTlo[(size_t)NG*DI];        // correction, x1024
static __device__ __align__(16) __half g_WhT[(size_t)NG*HID];         // [c'][k], K-major, fp16
static __device__ __align__(16) float  g_bias[NG];                    // c' order
static __device__ __align__(16) float  g_X[(size_t)TBM*NG];           // c' order
static __device__ __align__(16) __half g_HG[2][GRP][16*HID];          // per-group H, frag order
static __device__ int g_cntG[GRP*32];      // padded arrival counters
static __device__ int g_phaseG[GRP*32];    // padded phase flags
static __device__ int g_Xflag[256*32];     // per-row-block (2 timesteps) counters, padded

// ----------------- helpers -----------------
__device__ __forceinline__ void split_h16(float v, __half& hi, __half& lo) {
    hi = __float2half(v);
    lo = __float2half(v - __half2float(hi));
}

// D(f32) += A(f16) * B(f16), m16n8k16
__device__ __forceinline__ void mma16816(float* c,
                                         uint32_t a0, uint32_t a1, uint32_t a2, uint32_t a3,
                                         uint32_t b0, uint32_t b1) {
    asm volatile(
        "mma.sync.aligned.m16n8k16.row.col.f32.f16.f16.f32 "
        "{%0,%1,%2,%3},{%4,%5,%6,%7},{%8,%9},{%0,%1,%2,%3};\n"
        : "+f"(c[0]), "+f"(c[1]), "+f"(c[2]), "+f"(c[3])
        : "r"(a0), "r"(a1), "r"(a2), "r"(a3), "r"(b0), "r"(b1));
}

__device__ __forceinline__ uint32_t smem_u32(const void* p) {
    return (uint32_t)__cvta_generic_to_shared(p);
}

__device__ __forceinline__ void ldsm4(uint32_t* r, uint32_t addr) {
    asm volatile("ldmatrix.sync.aligned.m8n8.x4.shared.b16 {%0,%1,%2,%3}, [%4];"
        : "=r"(r[0]), "=r"(r[1]), "=r"(r[2]), "=r"(r[3]) : "r"(addr));
}

__device__ __forceinline__ float sigf(float x) { return 1.f / (1.f + __expf(-x)); }
__device__ __forceinline__ float tanhfast(float x) {
    float ax = fminf(fmaxf(x, -15.f), 15.f);
    float e  = __expf(2.f * ax);
    return (e - 1.f) / (e + 1.f);
}

__device__ __forceinline__ void cpa16(void* dst, const void* src) {
    uint32_t s = smem_u32(dst);
    asm volatile("cp.async.cg.shared.global [%0], [%1], 16;\n" :: "r"(s), "l"(src));
}
__device__ __forceinline__ void cpa_commit() { asm volatile("cp.async.commit_group;\n"); }
template<int N> __device__ __forceinline__ void cpa_wait() {
    asm volatile("cp.async.wait_group %0;\n" :: "n"(N));
}

// ----------------- per-group barrier (two-hop: counter + clean phase line) -----------------
__device__ __forceinline__ void barg_wait(int* phs, int target) {
    if (threadIdx.x == 0) {
        int v;
        do {
            asm volatile("ld.acquire.gpu.global.s32 %0, [%1];" : "=r"(v) : "l"(phs) : "memory");
        } while (v < target);
    }
    __syncthreads();
}

// all-threads poll: X row-block rb (2 timesteps) complete when counter == 16
__device__ __forceinline__ void wait_x(int rb) {
    const int* f = &g_Xflag[rb*32];
    int v;
    do {
        asm volatile("ld.acquire.gpu.global.s32 %0, [%1];" : "=r"(v) : "l"(f) : "memory");
    } while (v < 16);
}

// ----------------- init -----------------
__global__ void k_init() {
    int i = blockIdx.x * blockDim.x + threadIdx.x;
    if (i < 2 * GRP * 16 * HID) ((__half*)g_HG)[i] = __float2half(0.f);
    if (i < GRP*32) { g_cntG[i] = 0; g_phaseG[i] = 0; }
    if (i < 256*32) g_Xflag[i] = 0;
}

// ----------------- inputs -> fp16 -----------------
__global__ void k_conv_in(const float* __restrict__ in) {
    size_t i = (size_t)blockIdx.x * blockDim.x + threadIdx.x;
    const size_t n4 = (size_t)TBM * DI / 4;
    if (i >= n4) return;
    float4 v = reinterpret_cast<const float4*>(in)[i];
    __half2* ph = reinterpret_cast<__half2*>(g_A + 4*i);
    ph[0] = __halves2half2(__float2half(v.x), __float2half(v.y));
    ph[1] = __halves2half2(__float2half(v.z), __float2half(v.w));
}

// ----------------- weights -> fp16, transposed, gate-interleaved c' = h*4+g -----------------
__global__ void k_conv_w(const float* __restrict__ Wxi, const float* __restrict__ Wxf,
                         const float* __restrict__ Wxo, const float* __restrict__ Wxc,
                         const float* __restrict__ Whi, const float* __restrict__ Whf,
                         const float* __restrict__ Who, const float* __restrict__ Whc,
                         const float* __restrict__ bi,  const float* __restrict__ bff,
                         const float* __restrict__ bo,  const float* __restrict__ bc) {
    const int NW = NG * DI;
    int stride = gridDim.x * blockDim.x;
    for (int i = blockIdx.x * blockDim.x + threadIdx.x; i < 2*NW + NG; i += stride) {
        if (i < NW) {                          // WxT[c'][d], split, scaled
            int c = i >> 9, d = i & 511;
            int h = c >> 2, gg = c & 3;
            const float* W = gg == 0 ? Wxi : (gg == 1 ? Wxf : (gg == 2 ? Wxo : Wxc));
            __half hi, lo; split_h16(W[d*HID + h] * WSCALE, hi, lo);
            g_WxThi[i] = hi; g_WxTlo[i] = lo;
        } else if (i < 2*NW) {                 // WhT[c'][k], fp16
            int jj = i - NW;
            int c = jj >> 9, k = jj & 511;
            int h = c >> 2, gg = c & 3;
            const float* W = gg == 0 ? Whi : (gg == 1 ? Whf : (gg == 2 ? Who : Whc));
            g_WhT[jj] = __float2half(W[k*HID + h]);
        } else {                               // bias, c' order
            int c = i - 2*NW;
            int h = c >> 2, gg = c & 3;
            const float* bb = gg == 0 ? bi : (gg == 1 ? bff : (gg == 2 ? bo : bc));
            g_bias[c] = bb[h];
        }
    }
}

// ----------------- gemm tile (device fn; one 128x128 output tile; 2-term fp16) -----------------
__device__ __forceinline__ void gx_prefetch(__half* smx, int ck, int s,
                                            int row0, int col0, int lr, int lh) {
    size_t gA = (size_t)(row0 + lr) * DI + ck*KCH + lh*8;
    size_t gB = (size_t)(col0 + lr) * DI + ck*KCH + lh*8;
    int so = lr*GPAD + lh*8;
    __half* base = smx + (size_t)s*GSTG;
    cpa16(base + 0*GTILE + so, g_A     + gA);
    cpa16(base + 1*GTILE + so, g_WxThi + gB);
    cpa16(base + 2*GTILE + so, g_WxTlo + gB);
}

__device__ void gemm_tile(__half* smx, int by, int bx) {
    const int tid = threadIdx.x, w = tid >> 5, l = tid & 31;
    const int wm = w & 3, wn = w >> 2, r = l >> 2, q = l & 3;
    const int row0 = by * 128, col0 = bx * 128;
    const int lr = tid >> 1, lh = tid & 1;
    const int grp = l >> 3, rr = l & 7;
    const int NK = DI / KCH;   // 32

    float acc[2][8][4];
    #pragma unroll
    for (int a = 0; a < 2; a++)
        #pragma unroll
        for (int b = 0; b < 8; b++)
            #pragma unroll
            for (int c = 0; c < 4; c++) acc[a][b][c] = 0.f;

    gx_prefetch(smx, 0, 0, row0, col0, lr, lh);
    cpa_commit();
    gx_prefetch(smx, 1, 1, row0, col0, lr, lh);
    cpa_commit();

    for (int ck = 0; ck < NK; ck++) {
        cpa_wait<1>();
        __syncthreads();

        if (ck + 2 < NK) {
            gx_prefetch(smx, ck + 2, (ck + 2) % 3, row0, col0, lr, lh);
            cpa_commit();
        } else {
            cpa_commit();
        }

        const __half* base = smx + (size_t)(ck % 3)*GSTG;
        const __half* Ah_s = base + 0*GTILE;
        const __half* Bh_s = base + 1*GTILE;
        const __half* Bl_s = base + 2*GTILE;

        const int acol = (grp >> 1)*8;
        uint32_t Ahf[2][4];
        #pragma unroll
        for (int mt = 0; mt < 2; mt++) {
            int arow = wm*32 + mt*16 + (grp & 1)*8 + rr;
            ldsm4(Ahf[mt], smem_u32(&Ah_s[arow*GPAD + acol]));
        }
        #pragma unroll
        for (int np = 0; np < 4; np++) {
            int brow = wn*64 + np*16 + (grp >> 1)*8 + rr;
            int bcol = (grp & 1)*8;
            uint32_t bh[4], bl[4];
            ldsm4(bh, smem_u32(&Bh_s[brow*GPAD + bcol]));
            ldsm4(bl, smem_u32(&Bl_s[brow*GPAD + bcol]));
            #pragma unroll
            for (int mt = 0; mt < 2; mt++) {
                float* a0 = acc[mt][np*2];
                float* a1 = acc[mt][np*2 + 1];
                mma16816(a0, Ahf[mt][0], Ahf[mt][1], Ahf[mt][2], Ahf[mt][3], bh[0], bh[1]);
                mma16816(a0, Ahf[mt][0], Ahf[mt][1], Ahf[mt][2], Ahf[mt][3], bl[0], bl[1]);
                mma16816(a1, Ahf[mt][0], Ahf[mt][1], Ahf[mt][2], Ahf[mt][3], bh[2], bh[3]);
                mma16816(a1, Ahf[mt][0], Ahf[mt][1], Ahf[mt][2], Ahf[mt][3], bl[2], bl[3]);
            }
        }
    }

    const float ISC = 1.0f / WSCALE;
    #pragma unroll
    for (int mt = 0; mt < 2; mt++) {
        #pragma unroll
        for (int nt = 0; nt < 8; nt++) {
            int grow = row0 + wm*32 + mt*16 + r;
            int gcol = col0 + wn*64 + nt*8 + 2*q;
            float2 bb = *(const float2*)&g_bias[gcol];
            float2 v0 = make_float2(acc[mt][nt][0]*ISC + bb.x, acc[mt][nt][1]*ISC + bb.y);
            float2 v1 = make_float2(acc[mt][nt][2]*ISC + bb.x, acc[mt][nt][3]*ISC + bb.y);
            *(float2*)&g_X[(size_t)grow * NG + gcol]       = v0;
            *(float2*)&g_X[(size_t)(grow + 8) * NG + gcol] = v1;
        }
    }

    // publish: row-block by ready when all 16 col blocks arrive
    __syncthreads();
    if (threadIdx.x == 0) {
        asm volatile("red.release.gpu.global.add.s32 [%0], %1;"
                     :: "l"(&g_Xflag[by*32]), "r"(1) : "memory");
    }
    // drain committed cp.asyncs before smem reuse on next tile
    cpa_wait<0>();
    __syncthreads();
}

// ----------------- lstm role (device fn) -----------------
__device__ void lstm_body(float* __restrict__ out, char* dynsm, int blk) {
    __half* sH    = (__half*)dynsm;                  // 16KB H copy
    __half* sOut  = (__half*)(dynsm + 16384);        // 512B H publish staging
    float*  sOutF = (float*)(dynsm + 16896);         // 1KB fp32 out staging

    const int tid = threadIdx.x, w = tid >> 5, l = tid & 31;
    const int r = l >> 2, q = l & 3;
    const int g = blk >> 5, j = blk & 31;
    int* cnt = &g_cntG[g*32];
    int* phs = &g_phaseG[g*32];

    // Wh fragments in registers: warp's col = j*64 + w*8 + r, all 32 k-frags
    uint32_t Bh[32][2];
    {
        const __half* wp = g_WhT + (size_t)(j*64 + w*8 + r) * HID;
        #pragma unroll
        for (int ktl = 0; ktl < 32; ktl++) {
            int kg = ktl * 16;
            Bh[ktl][0] = *(const uint32_t*)(wp + kg + 2*q);
            Bh[ktl][1] = *(const uint32_t*)(wp + kg + 2*q + 8);
        }
    }

    float C = 0.f;
    const int myrow = (q & 1) ? (r + 8) : r;
    const int hid   = j*16 + w*2 + (q >> 1);
    const int col   = w*2 + (q >> 1);
    const int kk    = hid & 15;
    const int plane = ((myrow & 7) << 2) | ((kk & 7) >> 1);
    const int preg  = ((myrow >> 3) & 1) | ((kk >> 3) << 1);
    const int sloc  = plane*8 + preg*2 + (kk & 1);
    const int c0    = j*64 + w*8 + 2*q;

    // wait for X row-block 0, then prefetch t=0 seeds
    wait_x(0);
    float2 sd01, sd23;
    {
        size_t row0 = (size_t)(g*16 + r);
        sd01 = __ldcg((const float2*)&g_X[row0 * NG + c0]);
        sd23 = __ldcg((const float2*)&g_X[(row0 + 8) * NG + c0]);
    }

    for (int t = 0; t < TS; t++) {
        const int rb = t & 1;
        float acc[4], acc2[4];
        acc[0] = sd01.x; acc[1] = sd01.y; acc[2] = sd23.x; acc[3] = sd23.y;
        acc2[0] = acc2[1] = acc2[2] = acc2[3] = 0.f;

        if (t > 0) barg_wait(phs, t);   // group's H(t-1) visible

        // chunked cooperative H copy: 2 x 8KB via cp.async
        const __half* Hg = g_HG[rb][g];
        cpa16(sH + (size_t)tid*8,         Hg + (size_t)tid*8);
        cpa16(sH + (size_t)(tid+256)*8,   Hg + (size_t)(tid+256)*8);
        cpa_commit();
        cpa16(sH + (size_t)(tid+512)*8,   Hg + (size_t)(tid+512)*8);
        cpa16(sH + (size_t)(tid+768)*8,   Hg + (size_t)(tid+768)*8);
        cpa_commit();

        // prefetch seeds for t+1 (new X row-block every 2 steps; poll its flag)
        if (t + 1 < TS) {
            if (((t + 1) & 1) == 0) wait_x((t + 1) >> 1);
            size_t rown = (size_t)((t + 1)*BA + g*16 + r);
            sd01 = __ldcg((const float2*)&g_X[rown * NG + c0]);
            sd23 = __ldcg((const float2*)&g_X[(rown + 8) * NG + c0]);
        }

        cpa_wait<1>();
        __syncthreads();
        #pragma unroll
        for (int ktl = 0; ktl < 16; ktl += 2) {
            uint4 a0 = *(const uint4*)(sH + (size_t)(ktl*32 + l)*8);
            uint4 a1 = *(const uint4*)(sH + (size_t)((ktl + 1)*32 + l)*8);
            mma16816(acc,  a0.x, a0.y, a0.z, a0.w, Bh[ktl][0],   Bh[ktl][1]);
            mma16816(acc2, a1.x, a1.y, a1.z, a1.w, Bh[ktl+1][0], Bh[ktl+1][1]);
        }
        cpa_wait<0>();
        __syncthreads();
        #pragma unroll
        for (int ktl = 16; ktl < 32; ktl += 2) {
            uint4 a0 = *(const uint4*)(sH + (size_t)(ktl*32 + l)*8);
            uint4 a1 = *(const uint4*)(sH + (size_t)((ktl + 1)*32 + l)*8);
            mma16816(acc,  a0.x, a0.y, a0.z, a0.w, Bh[ktl][0],   Bh[ktl][1]);
            mma16816(acc2, a1.x, a1.y, a1.z, a1.w, Bh[ktl+1][0], Bh[ktl+1][1]);
        }
        acc[0] += acc2[0]; acc[1] += acc2[1]; acc[2] += acc2[2]; acc[3] += acc2[3];

        // gather 4 gates into one thread via lane-pair shuffle
        float s0 = __shfl_xor_sync(0xffffffffu, acc[0], 1);
        float s1 = __shfl_xor_sync(0xffffffffu, acc[1], 1);
        float s2 = __shfl_xor_sync(0xffffffffu, acc[2], 1);
        float s3 = __shfl_xor_sync(0xffffffffu, acc[3], 1);
        float xi, xf, xo, xc;
        if (q & 1) { xi = s2;     xf = s3;     xo = acc[2]; xc = acc[3]; }
        else       { xi = acc[0]; xf = acc[1]; xo = s0;     xc = s1;     }

        float I  = sigf(xi), F = sigf(xf), O = sigf(xo);
        float Ct = tanhfast(xc);
        C = F*C + I*Ct;
        float Hn = O * tanhfast(C);

        // stage H (fp16, frag order) + fp32 out tile in smem
        sOut[sloc] = __float2half(Hn);
        sOutF[myrow*16 + col] = Hn;
        __syncthreads();   // orders: sOut/sOutF writes, sH reuse, all pre-publish work
        if (tid < 32) {
            uint4 v = *(const uint4*)(sOut + tid*8);
            __half* dst = &g_HG[rb ^ 1][g][j*256 + tid*8];
            asm volatile("st.global.cg.v4.u32 [%0], {%1,%2,%3,%4};"
                         :: "l"(dst), "r"(v.x), "r"(v.y), "r"(v.z), "r"(v.w) : "memory");
            __syncwarp();
            if (tid == 0) {
                int old;
                asm volatile("atom.release.gpu.global.add.s32 %0, [%1], %2;"
                             : "=r"(old) : "l"(cnt), "r"(1) : "memory");
                if (old == BPG - 1) {
                    asm volatile("st.relaxed.gpu.global.s32 [%0], %1;" :: "l"(cnt), "r"(0) : "memory");
                    asm volatile("st.release.gpu.global.s32 [%0], %1;" :: "l"(phs), "r"(t + 1) : "memory");
                }
            }
        }

        // off the critical path: coalesced fp32 outputs
        {
            int orow = tid >> 4, ocol = tid & 15;
            out[((size_t)t*BA + g*16 + orow)*HID + j*16 + ocol] = sOutF[tid];
        }
        if (t == TS - 1) {
            int batch = g*16 + myrow;
            out[(size_t)TS*BA*HID + (size_t)batch*HID + hid]                  = Hn;
            out[(size_t)TS*BA*HID + (size_t)BA*HID + (size_t)batch*HID + hid] = C;
        }
    }
}

// ----------------- fused kernel: lstm blocks 0..127, gemm workers 128..295 -----------------
__global__ __launch_bounds__(256, 2) void k_fused(float* __restrict__ out) {
    extern __shared__ char dynsm[];
    const int bid = blockIdx.x;
    if (bid < NLSTM) {
        lstm_body(out, dynsm, bid);
    } else {
        const int wkr = bid - NLSTM;
        __half* smx = (__half*)dynsm;
        for (int tile = wkr; tile < 256*16; tile += NWKR) {
            gemm_tile(smx, tile >> 4, tile & 15);
        }
    }
}

// ----------------- launch -----------------
extern "C" void kernel_launch(void* const* d_in, const int* in_sizes, int n_in,
                              void* d_out, int out_size) {
    const float* inp = (const float*)d_in[0];
    const float* Wxi = (const float*)d_in[1];
    const float* Whi = (const float*)d_in[2];
    const float* bi  = (const float*)d_in[3];
    const float* Wxf = (const float*)d_in[4];
    const float* Whf = (const float*)d_in[5];
    const float* bf  = (const float*)d_in[6];
    const float* Wxo = (const float*)d_in[7];
    const float* Who = (const float*)d_in[8];
    const float* bo  = (const float*)d_in[9];
    const float* Wxc = (const float*)d_in[10];
    const float* Whc = (const float*)d_in[11];
    const float* bc  = (const float*)d_in[12];
    float* out = (float*)d_out;

    static int inited = 0;
    if (!inited) {
        cudaFuncSetAttribute(k_fused, cudaFuncAttributeMaxDynamicSharedMemorySize, GSMEM);
        inited = 1;
    }

    k_init<<<256, 256>>>();
    k_conv_in<<<16384, 256>>>(inp);
    k_conv_w<<<2048, 256>>>(Wxi, Wxf, Wxo, Wxc, Whi, Whf, Who, Whc, bi, bf, bo, bc);
    k_fused<<<NLSTM + NWKR, 256, GSMEM>>>(out);
}